// round 3
// baseline (speedup 1.0000x reference)
#include <cuda_runtime.h>

#define BB 2
#define DD 128
#define OD 123   // 128 - 6 + 1
typedef unsigned long long ull;

// scratch: dense grid [B,128,128,128,3] (x,ch interleaved; row pitch 384 floats)
__device__ float g_dense[BB*DD*DD*DD*3 + 1024];
// composed weights, padded layout [sz][sy][i*3+o][8]: slots of 8 floats, w0..w5 + pad
__device__ float g_weff[6*6*9*8];

static __device__ __forceinline__ ull pack2(float lo, float hi) {
    ull r;
    asm("mov.b64 %0, {%1, %2};" : "=l"(r) : "f"(lo), "f"(hi));
    return r;
}
static __device__ __forceinline__ void fma2(ull &d, ull a, ull b) {
    asm("fma.rn.f32x2 %0, %1, %2, %0;" : "+l"(d) : "l"(a), "l"(b));
}
static __device__ __forceinline__ float2 unpack2(ull v) {
    float2 f;
    asm("mov.b64 {%0, %1}, %2;" : "=f"(f.x), "=f"(f.y) : "l"(v));
    return f;
}

__global__ void zero_kernel(int n4) {
    int i = blockIdx.x * blockDim.x + threadIdx.x;
    float4* p = (float4*)g_dense;
    float4 z = make_float4(0.f, 0.f, 0.f, 0.f);
    for (; i < n4; i += gridDim.x * blockDim.x) p[i] = z;
}

__global__ void scatter_kernel(const int* __restrict__ coords,
                               const float* __restrict__ voxels, int n) {
    int i = blockIdx.x * blockDim.x + threadIdx.x;
    if (i >= n) return;
    int b = coords[4*i+0], z = coords[4*i+1], y = coords[4*i+2], x = coords[4*i+3];
    int base = (((b*DD + z)*DD + y)*DD + x) * 3;
    atomicAdd(&g_dense[base+0], voxels[3*i+0]);
    atomicAdd(&g_dense[base+1], voxels[3*i+1]);
    atomicAdd(&g_dense[base+2], voxels[3*i+2]);
}

// Compose Weff = W1 (*) W2 (*) W3 (all linear, valid correlation composition)
__global__ void weff_kernel(const float* __restrict__ W1,
                            const float* __restrict__ W2,
                            const float* __restrict__ W3) {
    __shared__ float W12[4*4*4*3*5];   // [uz][uy][ux][i][m]
    int tid = threadIdx.x;
    for (int idx = tid; idx < 960; idx += blockDim.x) {
        int m = idx % 5, i = (idx/5) % 3, u = idx / 15;
        int ux = u % 4, uy = (u/4) % 4, uz = u / 16;
        float s = 0.f;
        for (int qz = 0; qz < 2; qz++) { int rz = uz - qz; if (rz < 0 || rz > 2) continue;
        for (int qy = 0; qy < 2; qy++) { int ry = uy - qy; if (ry < 0 || ry > 2) continue;
        for (int qx = 0; qx < 2; qx++) { int rx = ux - qx; if (rx < 0 || rx > 2) continue;
            const float* w1 = W1 + ((qz*2+qy)*2+qx)*27 + i*9;      // [.,i,c]
            const float* w2 = W2 + ((rz*3+ry)*3+rx)*45 + m;        // [.,c,m]
            for (int c = 0; c < 9; c++) s += w1[c] * w2[c*5];
        }}}
        W12[idx] = s;
    }
    __syncthreads();
    for (int idx = tid; idx < 5832; idx += blockDim.x) {
        int o = idx % 3, i = (idx/3) % 3, sp = idx / 9;
        int sx = sp % 6, sy = (sp/6) % 6, sz = sp / 36;
        float s = 0.f;
        for (int uz = 0; uz < 4; uz++) { int tz = sz - uz; if (tz < 0 || tz > 2) continue;
        for (int uy = 0; uy < 4; uy++) { int ty = sy - uy; if (ty < 0 || ty > 2) continue;
        for (int ux = 0; ux < 4; ux++) { int tx = sx - ux; if (tx < 0 || tx > 2) continue;
            const float* w12 = W12 + ((uz*4+uy)*4+ux)*15 + i*5;    // [.,i,m]
            const float* w3  = W3  + ((tz*3+ty)*3+tx)*15 + o;      // [.,m,o]
            for (int m = 0; m < 5; m++) s += w12[m] * w3[m*3];
        }}}
        g_weff[((sz*6+sy)*9 + (i*3+o))*8 + sx] = s;   // padded slot of 8
    }
}

// Fused gather conv: out = relu(dense (*) Weff + b3)
// block: 128 threads = 32 x-groups * 4 ty; thread computes RX=4 x * RY=2 y * 3 ch
// block output tile: z fixed, y0..y0+7, x 0..127 (stores guarded to OD)
__global__ void __launch_bounds__(128, 4) conv_kernel(const float* __restrict__ b3,
                                                      float* __restrict__ out) {
    __shared__ float s_in[13*384];     // 13 input rows, pitch 384 floats
    __shared__ float s_w[6*6*9*8];     // full composed weights

    // copy weights to smem (coalesced, once)
    {
        const float4* src = (const float4*)g_weff;
        float4* dst = (float4*)s_w;
        for (int idx = threadIdx.x; idx < (6*6*9*8)/4; idx += 128) dst[idx] = src[idx];
    }

    int tx = threadIdx.x & 31, ty = threadIdx.x >> 5;
    int y0 = blockIdx.y * 8;
    int zb = blockIdx.z;
    int b  = zb / OD, z = zb - b * OD;
    int x0 = tx * 4;

    ull accA[4][3], accB[4][3];
    #pragma unroll
    for (int rx = 0; rx < 4; rx++)
        #pragma unroll
        for (int o = 0; o < 3; o++) { accA[rx][o] = 0ULL; accB[rx][o] = 0ULL; }

    const int rowpitch = DD*3;          // 384
    const float* gz = g_dense + (b*DD + z) * (DD*rowpitch);

    #pragma unroll 1
    for (int sz = 0; sz < 6; sz++) {
        __syncthreads();   // previous compute done before overwrite
        // cooperative coalesced load of 13 rows (y0 .. y0+12, clamped)
        const float* gp = gz + sz * (DD*rowpitch);
        #pragma unroll 1
        for (int idx = threadIdx.x; idx < 13*96; idx += 128) {   // 96 float4 per row
            int r = idx / 96, c = idx - r * 96;
            int yr = y0 + r; if (yr > 127) yr = 127;
            ((float4*)s_in)[r*96 + c] = ((const float4*)(gp + yr*rowpitch))[c];
        }
        __syncthreads();

        // warp ty: outputs yA=y0+2ty (sy=t), yB=yA+1 (sy=t-1); rows t=0..6
        #pragma unroll
        for (int t = 0; t < 7; t++) {
            const float* rp = s_in + (2*ty + t)*384 + x0*3;
            float in[28];
            #pragma unroll
            for (int k = 0; k < 7; k++) {
                float4 v = *(const float4*)(rp + 4*k);
                in[4*k+0] = v.x; in[4*k+1] = v.y; in[4*k+2] = v.z; in[4*k+3] = v.w;
            }
            #pragma unroll
            for (int i = 0; i < 3; i++) {
                ull q[8];
                #pragma unroll
                for (int k = 0; k < 8; k++) q[k] = pack2(in[k*3+i], in[k*3+3+i]);
                #pragma unroll
                for (int o = 0; o < 3; o++) {
                    if (t <= 5) {   // compile-time (t unrolled)
                        const float* w = s_w + ((sz*6 + t)*9 + i*3 + o)*8;
                        ull w01 = *(const ull*)(w);
                        ull w23 = *(const ull*)(w+2);
                        ull w45 = *(const ull*)(w+4);
                        #pragma unroll
                        for (int rx = 0; rx < 4; rx++) {
                            fma2(accA[rx][o], q[rx+0], w01);
                            fma2(accA[rx][o], q[rx+2], w23);
                            fma2(accA[rx][o], q[rx+4], w45);
                        }
                    }
                    if (t >= 1) {
                        const float* w = s_w + ((sz*6 + t-1)*9 + i*3 + o)*8;
                        ull w01 = *(const ull*)(w);
                        ull w23 = *(const ull*)(w+2);
                        ull w45 = *(const ull*)(w+4);
                        #pragma unroll
                        for (int rx = 0; rx < 4; rx++) {
                            fma2(accB[rx][o], q[rx+0], w01);
                            fma2(accB[rx][o], q[rx+2], w23);
                            fma2(accB[rx][o], q[rx+4], w45);
                        }
                    }
                }
            }
        }
    }

    float bias0 = b3[0], bias1 = b3[1], bias2 = b3[2];
    int yA = y0 + 2*ty, yB = yA + 1;
    if (yA < OD) {
        int ob = ((b*OD + z)*OD + yA)*OD;
        #pragma unroll
        for (int rx = 0; rx < 4; rx++) {
            int x = x0 + rx;
            if (x < OD) {
                float2 f0 = unpack2(accA[rx][0]);
                float2 f1 = unpack2(accA[rx][1]);
                float2 f2 = unpack2(accA[rx][2]);
                out[(ob + x)*3 + 0] = fmaxf(f0.x + f0.y + bias0, 0.f);
                out[(ob + x)*3 + 1] = fmaxf(f1.x + f1.y + bias1, 0.f);
                out[(ob + x)*3 + 2] = fmaxf(f2.x + f2.y + bias2, 0.f);
            }
        }
    }
    if (yB < OD) {
        int ob = ((b*OD + z)*OD + yB)*OD;
        #pragma unroll
        for (int rx = 0; rx < 4; rx++) {
            int x = x0 + rx;
            if (x < OD) {
                float2 f0 = unpack2(accB[rx][0]);
                float2 f1 = unpack2(accB[rx][1]);
                float2 f2 = unpack2(accB[rx][2]);
                out[(ob + x)*3 + 0] = fmaxf(f0.x + f0.y + bias0, 0.f);
                out[(ob + x)*3 + 1] = fmaxf(f1.x + f1.y + bias1, 0.f);
                out[(ob + x)*3 + 2] = fmaxf(f2.x + f2.y + bias2, 0.f);
            }
        }
    }
}

extern "C" void kernel_launch(void* const* d_in, const int* in_sizes, int n_in,
                              void* d_out, int out_size) {
    const int*   coords = (const int*)d_in[0];
    const float* voxels = (const float*)d_in[1];
    const float* W1 = (const float*)d_in[2];
    const float* W2 = (const float*)d_in[3];
    const float* W3 = (const float*)d_in[4];
    const float* b3 = (const float*)d_in[5];
    float* out = (float*)d_out;

    int n = in_sizes[0] / 4;   // coords is [N,4]

    int n4 = (BB*DD*DD*DD*3 + 1024) / 4;
    zero_kernel<<<1024, 256>>>(n4);
    scatter_kernel<<<(n + 255) / 256, 256>>>(coords, voxels, n);
    weff_kernel<<<1, 256>>>(W1, W2, W3);
    conv_kernel<<<dim3(1, 16, OD * BB), 128>>>(b3, out);
}

// round 7
// speedup vs baseline: 1.5932x; 1.5932x over previous
#include <cuda_runtime.h>

#define BB 2
#define DD 128
#define OD 123   // 128 - 6 + 1
#define PLN (BB*DD*DD*DD)   // one channel plane, floats
typedef unsigned long long ull;

// scratch: dense grid SoA [ch][b][z][y][x], 3 planes + pad for edge overreads
__device__ float g_dense[3*PLN + 64];
// composed weights, padded layout [sz][sy][i*3+o][8]: w_sx0..5 + 2 pad
__device__ float g_weff[6*6*9*8];

static __device__ __forceinline__ ull pack2(float lo, float hi) {
    ull r;
    asm("mov.b64 %0, {%1, %2};" : "=l"(r) : "f"(lo), "f"(hi));
    return r;
}
static __device__ __forceinline__ void fma2(ull &d, ull a, ull b) {
    asm("fma.rn.f32x2 %0, %1, %2, %0;" : "+l"(d) : "l"(a), "l"(b));
}
static __device__ __forceinline__ float2 unpack2(ull v) {
    float2 f;
    asm("mov.b64 {%0, %1}, %2;" : "=f"(f.x), "=f"(f.y) : "l"(v));
    return f;
}

__global__ void zero_kernel(int n4) {
    int i = blockIdx.x * blockDim.x + threadIdx.x;
    float4* p = (float4*)g_dense;
    float4 z = make_float4(0.f, 0.f, 0.f, 0.f);
    for (; i < n4; i += gridDim.x * blockDim.x) p[i] = z;
}

__global__ void scatter_kernel(const int* __restrict__ coords,
                               const float* __restrict__ voxels, int n) {
    int i = blockIdx.x * blockDim.x + threadIdx.x;
    if (i >= n) return;
    int b = coords[4*i+0], z = coords[4*i+1], y = coords[4*i+2], x = coords[4*i+3];
    int base = (((b*DD + z)*DD + y)*DD + x);
    atomicAdd(&g_dense[0*PLN + base], voxels[3*i+0]);
    atomicAdd(&g_dense[1*PLN + base], voxels[3*i+1]);
    atomicAdd(&g_dense[2*PLN + base], voxels[3*i+2]);
}

// Compose Weff = W1 (*) W2 (*) W3 (all linear, valid correlation composition)
__global__ void weff_kernel(const float* __restrict__ W1,
                            const float* __restrict__ W2,
                            const float* __restrict__ W3) {
    __shared__ float W12[4*4*4*3*5];   // [uz][uy][ux][i][m]
    int tid = threadIdx.x;
    for (int idx = tid; idx < 960; idx += blockDim.x) {
        int m = idx % 5, i = (idx/5) % 3, u = idx / 15;
        int ux = u % 4, uy = (u/4) % 4, uz = u / 16;
        float s = 0.f;
        for (int qz = 0; qz < 2; qz++) { int rz = uz - qz; if (rz < 0 || rz > 2) continue;
        for (int qy = 0; qy < 2; qy++) { int ry = uy - qy; if (ry < 0 || ry > 2) continue;
        for (int qx = 0; qx < 2; qx++) { int rx = ux - qx; if (rx < 0 || rx > 2) continue;
            const float* w1 = W1 + ((qz*2+qy)*2+qx)*27 + i*9;      // [.,i,c]
            const float* w2 = W2 + ((rz*3+ry)*3+rx)*45 + m;        // [.,c,m]
            for (int c = 0; c < 9; c++) s += w1[c] * w2[c*5];
        }}}
        W12[idx] = s;
    }
    __syncthreads();
    for (int idx = tid; idx < 5832; idx += blockDim.x) {
        int o = idx % 3, i = (idx/3) % 3, sp = idx / 9;
        int sx = sp % 6, sy = (sp/6) % 6, sz = sp / 36;
        float s = 0.f;
        for (int uz = 0; uz < 4; uz++) { int tz = sz - uz; if (tz < 0 || tz > 2) continue;
        for (int uy = 0; uy < 4; uy++) { int ty = sy - uy; if (ty < 0 || ty > 2) continue;
        for (int ux = 0; ux < 4; ux++) { int tx = sx - ux; if (tx < 0 || tx > 2) continue;
            const float* w12 = W12 + ((uz*4+uy)*4+ux)*15 + i*5;    // [.,i,m]
            const float* w3  = W3  + ((tz*3+ty)*3+tx)*15 + o;      // [.,m,o]
            for (int m = 0; m < 5; m++) s += w12[m] * w3[m*3];
        }}}
        g_weff[((sz*6+sy)*9 + (i*3+o))*8 + sx] = s;   // padded slot of 8
    }
}

// Fused gather conv over SoA planes: out = relu(dense (*) Weff + b3)
// block: 128 threads = 32 x-groups (RX=4) * 4 y; grid (1, 31, OD*BB)
__global__ void __launch_bounds__(128) conv_kernel(const float* __restrict__ b3,
                                                   float* __restrict__ out) {
    __shared__ float s_w[6*6*9*8];     // 10.1 KB
    {
        const float4* src = (const float4*)g_weff;
        float4* dst = (float4*)s_w;
        for (int idx = threadIdx.x; idx < (6*6*9*8)/4; idx += 128) dst[idx] = src[idx];
    }
    __syncthreads();

    int tx = threadIdx.x & 31, ty = threadIdx.x >> 5;
    int y  = blockIdx.y * 4 + ty;
    int zb = blockIdx.z;
    int b  = zb / OD, z = zb - b * OD;
    int x0 = tx * 4;
    if (y >= OD || x0 >= OD) return;

    ull acc[4][3];
    #pragma unroll
    for (int rx = 0; rx < 4; rx++)
        #pragma unroll
        for (int o = 0; o < 3; o++) acc[rx][o] = 0ULL;

    // row base in plane 0 (y uniform per warp -> uniform addressing + x0 lane part)
    const float* base = g_dense + ((b*DD + z)*DD + y)*DD + x0;

    #pragma unroll 1
    for (int sz = 0; sz < 6; sz++) {
      #pragma unroll
      for (int sy = 0; sy < 6; sy++) {
        const float* rp = base + (sz*DD + sy)*DD;
        const float* wr = s_w + (sz*6 + sy)*72;
        #pragma unroll
        for (int i = 0; i < 3; i++) {
            const float* pi = rp + i*PLN;
            float4 va = *(const float4*)pi;        // x0..x0+3
            float4 vb = *(const float4*)(pi + 4);  // x0+4..x0+7
            float  vc = pi[8];                     // x0+8
            // even pairs come free from the float4 register quads
            ull q0 = pack2(va.x, va.y), q2 = pack2(va.z, va.w);
            ull q4 = pack2(vb.x, vb.y), q6 = pack2(vb.z, vb.w);
            // odd pairs: 4 packs
            ull q1 = pack2(va.y, va.z), q3 = pack2(va.w, vb.x);
            ull q5 = pack2(vb.y, vb.z), q7 = pack2(vb.w, vc);
            #pragma unroll
            for (int o = 0; o < 3; o++) {
                const float* w = wr + (i*3 + o)*8;
                ull w01 = *(const ull*)(w);
                ull w23 = *(const ull*)(w+2);
                ull w45 = *(const ull*)(w+4);
                fma2(acc[0][o], q0, w01); fma2(acc[0][o], q2, w23); fma2(acc[0][o], q4, w45);
                fma2(acc[1][o], q1, w01); fma2(acc[1][o], q3, w23); fma2(acc[1][o], q5, w45);
                fma2(acc[2][o], q2, w01); fma2(acc[2][o], q4, w23); fma2(acc[2][o], q6, w45);
                fma2(acc[3][o], q3, w01); fma2(acc[3][o], q5, w23); fma2(acc[3][o], q7, w45);
            }
        }
      }
    }

    float bias0 = b3[0], bias1 = b3[1], bias2 = b3[2];
    int ob = ((b*OD + z)*OD + y)*OD;
    #pragma unroll
    for (int rx = 0; rx < 4; rx++) {
        int x = x0 + rx;
        if (x < OD) {
            float2 f0 = unpack2(acc[rx][0]);
            float2 f1 = unpack2(acc[rx][1]);
            float2 f2 = unpack2(acc[rx][2]);
            out[(ob + x)*3 + 0] = fmaxf(f0.x + f0.y + bias0, 0.f);
            out[(ob + x)*3 + 1] = fmaxf(f1.x + f1.y + bias1, 0.f);
            out[(ob + x)*3 + 2] = fmaxf(f2.x + f2.y + bias2, 0.f);
        }
    }
}

extern "C" void kernel_launch(void* const* d_in, const int* in_sizes, int n_in,
                              void* d_out, int out_size) {
    const int*   coords = (const int*)d_in[0];
    const float* voxels = (const float*)d_in[1];
    const float* W1 = (const float*)d_in[2];
    const float* W2 = (const float*)d_in[3];
    const float* W3 = (const float*)d_in[4];
    const float* b3 = (const float*)d_in[5];
    float* out = (float*)d_out;

    int n = in_sizes[0] / 4;   // coords is [N,4]

    int n4 = (3*PLN + 64) / 4;
    zero_kernel<<<1024, 256>>>(n4);
    scatter_kernel<<<(n + 255) / 256, 256>>>(coords, voxels, n);
    weff_kernel<<<1, 256>>>(W1, W2, W3);
    conv_kernel<<<dim3(1, 31, OD * BB), 128>>>(b3, out);
}

// round 10
// speedup vs baseline: 2.2441x; 1.4086x over previous
#include <cuda_runtime.h>

#define BB 2
#define DD 128
#define OD 123   // 128 - 6 + 1
#define PLN (BB*DD*DD*DD)   // one channel plane, floats
typedef unsigned long long ull;

// scratch: dense grid SoA [ch][b][z][y][x], 3 planes + pad for edge overreads
__device__ float g_dense[3*PLN + 64];
// composed weights, padded layout [sz][sy][i*3+o][8]: w_sx0..5 + 2 pad
__device__ float g_weff[6*6*9*8];
// same weights in constant memory (filled by D2D memcpyToSymbolAsync each launch)
__constant__ float c_w[6*6*9*8];

static __device__ __forceinline__ ull pack2(float lo, float hi) {
    ull r;
    asm("mov.b64 %0, {%1, %2};" : "=l"(r) : "f"(lo), "f"(hi));
    return r;
}
static __device__ __forceinline__ void fma2(ull &d, ull a, ull b) {
    asm("fma.rn.f32x2 %0, %1, %2, %0;" : "+l"(d) : "l"(a), "l"(b));
}
static __device__ __forceinline__ float2 unpack2(ull v) {
    float2 f;
    asm("mov.b64 {%0, %1}, %2;" : "=f"(f.x), "=f"(f.y) : "l"(v));
    return f;
}

__global__ void zero_kernel(int n4) {
    int i = blockIdx.x * blockDim.x + threadIdx.x;
    float4* p = (float4*)g_dense;
    float4 z = make_float4(0.f, 0.f, 0.f, 0.f);
    for (; i < n4; i += gridDim.x * blockDim.x) p[i] = z;
}

__global__ void scatter_kernel(const int* __restrict__ coords,
                               const float* __restrict__ voxels, int n) {
    int i = blockIdx.x * blockDim.x + threadIdx.x;
    if (i >= n) return;
    int b = coords[4*i+0], z = coords[4*i+1], y = coords[4*i+2], x = coords[4*i+3];
    int base = (((b*DD + z)*DD + y)*DD + x);
    atomicAdd(&g_dense[0*PLN + base], voxels[3*i+0]);
    atomicAdd(&g_dense[1*PLN + base], voxels[3*i+1]);
    atomicAdd(&g_dense[2*PLN + base], voxels[3*i+2]);
}

// Compose Weff = W1 (*) W2 (*) W3 (all linear, valid correlation composition)
__global__ void weff_kernel(const float* __restrict__ W1,
                            const float* __restrict__ W2,
                            const float* __restrict__ W3) {
    __shared__ float W12[4*4*4*3*5];   // [uz][uy][ux][i][m]
    int tid = threadIdx.x;
    for (int idx = tid; idx < 960; idx += blockDim.x) {
        int m = idx % 5, i = (idx/5) % 3, u = idx / 15;
        int ux = u % 4, uy = (u/4) % 4, uz = u / 16;
        float s = 0.f;
        for (int qz = 0; qz < 2; qz++) { int rz = uz - qz; if (rz < 0 || rz > 2) continue;
        for (int qy = 0; qy < 2; qy++) { int ry = uy - qy; if (ry < 0 || ry > 2) continue;
        for (int qx = 0; qx < 2; qx++) { int rx = ux - qx; if (rx < 0 || rx > 2) continue;
            const float* w1 = W1 + ((qz*2+qy)*2+qx)*27 + i*9;      // [.,i,c]
            const float* w2 = W2 + ((rz*3+ry)*3+rx)*45 + m;        // [.,c,m]
            for (int c = 0; c < 9; c++) s += w1[c] * w2[c*5];
        }}}
        W12[idx] = s;
    }
    __syncthreads();
    for (int idx = tid; idx < 5832; idx += blockDim.x) {
        int o = idx % 3, i = (idx/3) % 3, sp = idx / 9;
        int sx = sp % 6, sy = (sp/6) % 6, sz = sp / 36;
        float s = 0.f;
        for (int uz = 0; uz < 4; uz++) { int tz = sz - uz; if (tz < 0 || tz > 2) continue;
        for (int uy = 0; uy < 4; uy++) { int ty = sy - uy; if (ty < 0 || ty > 2) continue;
        for (int ux = 0; ux < 4; ux++) { int tx = sx - ux; if (tx < 0 || tx > 2) continue;
            const float* w12 = W12 + ((uz*4+uy)*4+ux)*15 + i*5;    // [.,i,m]
            const float* w3  = W3  + ((tz*3+ty)*3+tx)*15 + o;      // [.,m,o]
            for (int m = 0; m < 5; m++) s += w12[m] * w3[m*3];
        }}}
        g_weff[((sz*6+sy)*9 + (i*3+o))*8 + sx] = s;   // padded slot of 8
    }
}

// Fused gather conv over SoA planes, weights in constant memory.
// block: 128 threads = 32 x-groups (RX=4) * 4 warps(y); grid (1, 31, OD*BB)
__global__ void __launch_bounds__(128) conv_kernel(const float* __restrict__ b3,
                                                   float* __restrict__ out) {
    int tx = threadIdx.x & 31, ty = threadIdx.x >> 5;
    int y  = blockIdx.y * 4 + ty;      // uniform per warp
    int zb = blockIdx.z;
    int b  = zb / OD, z = zb - b * OD;
    int x0 = tx * 4;
    if (y >= OD) return;               // uniform exit; all 32 lanes stay for shfl

    ull acc[4][3];
    #pragma unroll
    for (int rx = 0; rx < 4; rx++)
        #pragma unroll
        for (int o = 0; o < 3; o++) acc[rx][o] = 0ULL;

    const float* base = g_dense + ((b*DD + z)*DD + y)*DD + x0;

    #pragma unroll 1
    for (int sz = 0; sz < 6; sz++) {
      #pragma unroll
      for (int sy = 0; sy < 6; sy++) {
        const float* rp = base + (sz*DD + sy)*DD;
        #pragma unroll
        for (int i = 0; i < 3; i++) {
            const float* pi = rp + i*PLN;
            float4 va = *(const float4*)pi;        // x0..x0+3
            float4 vb = *(const float4*)(pi + 4);  // x0+4..x0+7
            // x0+8 = lane (l+2)'s va.x ; lanes 30/31 get junk that only feeds
            // q7 -> acc[3] -> x=x0+3 >= OD for those lanes (never stored)
            float vc = __shfl_down_sync(0xffffffffu, va.x, 2);
            ull q0 = pack2(va.x, va.y), q2 = pack2(va.z, va.w);
            ull q4 = pack2(vb.x, vb.y), q6 = pack2(vb.z, vb.w);
            ull q1 = pack2(va.y, va.z), q3 = pack2(va.w, vb.x);
            ull q5 = pack2(vb.y, vb.z), q7 = pack2(vb.w, vc);
            #pragma unroll
            for (int o = 0; o < 3; o++) {
                const float* w = c_w + ((sz*6 + sy)*9 + i*3 + o)*8;
                ull w01 = *(const ull*)(w);
                ull w23 = *(const ull*)(w+2);
                ull w45 = *(const ull*)(w+4);
                fma2(acc[0][o], q0, w01); fma2(acc[0][o], q2, w23); fma2(acc[0][o], q4, w45);
                fma2(acc[1][o], q1, w01); fma2(acc[1][o], q3, w23); fma2(acc[1][o], q5, w45);
                fma2(acc[2][o], q2, w01); fma2(acc[2][o], q4, w23); fma2(acc[2][o], q6, w45);
                fma2(acc[3][o], q3, w01); fma2(acc[3][o], q5, w23); fma2(acc[3][o], q7, w45);
            }
        }
      }
    }

    float bias0 = b3[0], bias1 = b3[1], bias2 = b3[2];
    int ob = ((b*OD + z)*OD + y)*OD;
    #pragma unroll
    for (int rx = 0; rx < 4; rx++) {
        int x = x0 + rx;
        if (x < OD) {
            float2 f0 = unpack2(acc[rx][0]);
            float2 f1 = unpack2(acc[rx][1]);
            float2 f2 = unpack2(acc[rx][2]);
            out[(ob + x)*3 + 0] = fmaxf(f0.x + f0.y + bias0, 0.f);
            out[(ob + x)*3 + 1] = fmaxf(f1.x + f1.y + bias1, 0.f);
            out[(ob + x)*3 + 2] = fmaxf(f2.x + f2.y + bias2, 0.f);
        }
    }
}

extern "C" void kernel_launch(void* const* d_in, const int* in_sizes, int n_in,
                              void* d_out, int out_size) {
    const int*   coords = (const int*)d_in[0];
    const float* voxels = (const float*)d_in[1];
    const float* W1 = (const float*)d_in[2];
    const float* W2 = (const float*)d_in[3];
    const float* W3 = (const float*)d_in[4];
    const float* b3 = (const float*)d_in[5];
    float* out = (float*)d_out;

    int n = in_sizes[0] / 4;   // coords is [N,4]

    int n4 = (3*PLN + 64) / 4;
    zero_kernel<<<1024, 256>>>(n4);
    scatter_kernel<<<(n + 255) / 256, 256>>>(coords, voxels, n);
    weff_kernel<<<1, 256>>>(W1, W2, W3);

    // weights composed on device -> broadcast into constant bank (D2D, capturable)
    void* weff_dev = nullptr;
    cudaGetSymbolAddress(&weff_dev, g_weff);
    cudaMemcpyToSymbolAsync(c_w, weff_dev, sizeof(float)*6*6*9*8, 0,
                            cudaMemcpyDeviceToDevice);

    conv_kernel<<<dim3(1, 31, OD * BB), 128>>>(b3, out);
}

// round 16
// speedup vs baseline: 2.2875x; 1.0193x over previous
#include <cuda_runtime.h>

#define BB 2
#define DD 128
#define OD 123   // 128 - 6 + 1
#define PLN (BB*DD*DD*DD)   // one channel plane, floats
typedef unsigned long long ull;

// scratch: dense grid SoA [ch][b][z][y][x], 3 planes + pad for edge overreads
__device__ float g_dense[3*PLN + 64];
// composed weights, padded layout [sz][sy][i*3+o][8]: w_sx0..5 + 2 pad
__device__ float g_weff[6*6*9*8];
// same weights in constant memory (filled by D2D memcpyToSymbolAsync each launch)
__constant__ float c_w[6*6*9*8];

static __device__ __forceinline__ ull pack2(float lo, float hi) {
    ull r;
    asm("mov.b64 %0, {%1, %2};" : "=l"(r) : "f"(lo), "f"(hi));
    return r;
}
static __device__ __forceinline__ void fma2(ull &d, ull a, ull b) {
    asm("fma.rn.f32x2 %0, %1, %2, %0;" : "+l"(d) : "l"(a), "l"(b));
}
static __device__ __forceinline__ float2 unpack2(ull v) {
    float2 f;
    asm("mov.b64 {%0, %1}, %2;" : "=f"(f.x), "=f"(f.y) : "l"(v));
    return f;
}

__global__ void zero_kernel(int n4) {
    int i = blockIdx.x * blockDim.x + threadIdx.x;
    float4* p = (float4*)g_dense;
    float4 z = make_float4(0.f, 0.f, 0.f, 0.f);
    for (; i < n4; i += gridDim.x * blockDim.x) p[i] = z;
}

__global__ void scatter_kernel(const int* __restrict__ coords,
                               const float* __restrict__ voxels, int n) {
    int i = blockIdx.x * blockDim.x + threadIdx.x;
    if (i >= n) return;
    int b = coords[4*i+0], z = coords[4*i+1], y = coords[4*i+2], x = coords[4*i+3];
    int base = (((b*DD + z)*DD + y)*DD + x);
    atomicAdd(&g_dense[0*PLN + base], voxels[3*i+0]);
    atomicAdd(&g_dense[1*PLN + base], voxels[3*i+1]);
    atomicAdd(&g_dense[2*PLN + base], voxels[3*i+2]);
}

// Compose Weff = W1 (*) W2 (*) W3 (all linear, valid correlation composition)
__global__ void weff_kernel(const float* __restrict__ W1,
                            const float* __restrict__ W2,
                            const float* __restrict__ W3) {
    __shared__ float W12[4*4*4*3*5];   // [uz][uy][ux][i][m]
    int tid = threadIdx.x;
    for (int idx = tid; idx < 960; idx += blockDim.x) {
        int m = idx % 5, i = (idx/5) % 3, u = idx / 15;
        int ux = u % 4, uy = (u/4) % 4, uz = u / 16;
        float s = 0.f;
        for (int qz = 0; qz < 2; qz++) { int rz = uz - qz; if (rz < 0 || rz > 2) continue;
        for (int qy = 0; qy < 2; qy++) { int ry = uy - qy; if (ry < 0 || ry > 2) continue;
        for (int qx = 0; qx < 2; qx++) { int rx = ux - qx; if (rx < 0 || rx > 2) continue;
            const float* w1 = W1 + ((qz*2+qy)*2+qx)*27 + i*9;      // [.,i,c]
            const float* w2 = W2 + ((rz*3+ry)*3+rx)*45 + m;        // [.,c,m]
            for (int c = 0; c < 9; c++) s += w1[c] * w2[c*5];
        }}}
        W12[idx] = s;
    }
    __syncthreads();
    for (int idx = tid; idx < 5832; idx += blockDim.x) {
        int o = idx % 3, i = (idx/3) % 3, sp = idx / 9;
        int sx = sp % 6, sy = (sp/6) % 6, sz = sp / 36;
        float s = 0.f;
        for (int uz = 0; uz < 4; uz++) { int tz = sz - uz; if (tz < 0 || tz > 2) continue;
        for (int uy = 0; uy < 4; uy++) { int ty = sy - uy; if (ty < 0 || ty > 2) continue;
        for (int ux = 0; ux < 4; ux++) { int tx = sx - ux; if (tx < 0 || tx > 2) continue;
            const float* w12 = W12 + ((uz*4+uy)*4+ux)*15 + i*5;    // [.,i,m]
            const float* w3  = W3  + ((tz*3+ty)*3+tx)*15 + o;      // [.,m,o]
            for (int m = 0; m < 5; m++) s += w12[m] * w3[m*3];
        }}}
        g_weff[((sz*6+sy)*9 + (i*3+o))*8 + sx] = s;   // padded slot of 8
    }
}

// Fused gather conv, SoA planes, constant-bank weights, RY=2 y-blocking.
// block: 128 threads = 32 x-groups (RX=4) * 4 warps; warp handles outputs
// yA = by*8 + ty*2 and yB = yA+1. Each input row feeds both outputs' taps.
__global__ void __launch_bounds__(128) conv_kernel(const float* __restrict__ b3,
                                                   float* __restrict__ out) {
    int tx = threadIdx.x & 31, ty = threadIdx.x >> 5;
    int yA = blockIdx.y * 8 + ty * 2;  // uniform per warp
    int zb = blockIdx.z;
    int b  = zb / OD, z = zb - b * OD;
    int x0 = tx * 4;
    if (yA >= OD) return;              // warp-uniform exit; shfl mask stays full
    int yB = yA + 1;

    ull accA[4][3], accB[4][3];
    #pragma unroll
    for (int rx = 0; rx < 4; rx++)
        #pragma unroll
        for (int o = 0; o < 3; o++) { accA[rx][o] = 0ULL; accB[rx][o] = 0ULL; }

    #pragma unroll 1
    for (int sz = 0; sz < 6; sz++) {
      const float* slab = g_dense + ((b*DD + z + sz)*DD)*DD + x0;
      #pragma unroll
      for (int t = 0; t < 7; t++) {
        int yr = yA + t;
        if (yr > 127) yr = 127;        // only fires when yA=122 (yB invalid)
        const float* rp = slab + yr*DD;
        #pragma unroll
        for (int i = 0; i < 3; i++) {
            const float* pi = rp + i*PLN;
            float4 va = *(const float4*)pi;        // x0..x0+3
            float4 vb = *(const float4*)(pi + 4);  // x0+4..x0+7
            // x0+8 from lane l+2; junk in lanes 30/31 feeds only guarded outputs
            float vc = __shfl_down_sync(0xffffffffu, va.x, 2);
            ull q0 = pack2(va.x, va.y), q2 = pack2(va.z, va.w);
            ull q4 = pack2(vb.x, vb.y), q6 = pack2(vb.z, vb.w);
            ull q1 = pack2(va.y, va.z), q3 = pack2(va.w, vb.x);
            ull q5 = pack2(vb.y, vb.z), q7 = pack2(vb.w, vc);
            #pragma unroll
            for (int o = 0; o < 3; o++) {
                if (t <= 5) {          // compile-time (t unrolled): outA tap sy=t
                    const float* w = c_w + ((sz*6 + t)*9 + i*3 + o)*8;
                    ull w01 = *(const ull*)(w);
                    ull w23 = *(const ull*)(w+2);
                    ull w45 = *(const ull*)(w+4);
                    fma2(accA[0][o], q0, w01); fma2(accA[0][o], q2, w23); fma2(accA[0][o], q4, w45);
                    fma2(accA[1][o], q1, w01); fma2(accA[1][o], q3, w23); fma2(accA[1][o], q5, w45);
                    fma2(accA[2][o], q2, w01); fma2(accA[2][o], q4, w23); fma2(accA[2][o], q6, w45);
                    fma2(accA[3][o], q3, w01); fma2(accA[3][o], q5, w23); fma2(accA[3][o], q7, w45);
                }
                if (t >= 1) {          // outB tap sy=t-1
                    const float* w = c_w + ((sz*6 + t-1)*9 + i*3 + o)*8;
                    ull w01 = *(const ull*)(w);
                    ull w23 = *(const ull*)(w+2);
                    ull w45 = *(const ull*)(w+4);
                    fma2(accB[0][o], q0, w01); fma2(accB[0][o], q2, w23); fma2(accB[0][o], q4, w45);
                    fma2(accB[1][o], q1, w01); fma2(accB[1][o], q3, w23); fma2(accB[1][o], q5, w45);
                    fma2(accB[2][o], q2, w01); fma2(accB[2][o], q4, w23); fma2(accB[2][o], q6, w45);
                    fma2(accB[3][o], q3, w01); fma2(accB[3][o], q5, w23); fma2(accB[3][o], q7, w45);
                }
            }
        }
      }
    }

    float bias0 = b3[0], bias1 = b3[1], bias2 = b3[2];
    {
        int ob = ((b*OD + z)*OD + yA)*OD;
        #pragma unroll
        for (int rx = 0; rx < 4; rx++) {
            int x = x0 + rx;
            if (x < OD) {
                float2 f0 = unpack2(accA[rx][0]);
                float2 f1 = unpack2(accA[rx][1]);
                float2 f2 = unpack2(accA[rx][2]);
                out[(ob + x)*3 + 0] = fmaxf(f0.x + f0.y + bias0, 0.f);
                out[(ob + x)*3 + 1] = fmaxf(f1.x + f1.y + bias1, 0.f);
                out[(ob + x)*3 + 2] = fmaxf(f2.x + f2.y + bias2, 0.f);
            }
        }
    }
    if (yB < OD) {
        int ob = ((b*OD + z)*OD + yB)*OD;
        #pragma unroll
        for (int rx = 0; rx < 4; rx++) {
            int x = x0 + rx;
            if (x < OD) {
                float2 f0 = unpack2(accB[rx][0]);
                float2 f1 = unpack2(accB[rx][1]);
                float2 f2 = unpack2(accB[rx][2]);
                out[(ob + x)*3 + 0] = fmaxf(f0.x + f0.y + bias0, 0.f);
                out[(ob + x)*3 + 1] = fmaxf(f1.x + f1.y + bias1, 0.f);
                out[(ob + x)*3 + 2] = fmaxf(f2.x + f2.y + bias2, 0.f);
            }
        }
    }
}

extern "C" void kernel_launch(void* const* d_in, const int* in_sizes, int n_in,
                              void* d_out, int out_size) {
    const int*   coords = (const int*)d_in[0];
    const float* voxels = (const float*)d_in[1];
    const float* W1 = (const float*)d_in[2];
    const float* W2 = (const float*)d_in[3];
    const float* W3 = (const float*)d_in[4];
    const float* b3 = (const float*)d_in[5];
    float* out = (float*)d_out;

    int n = in_sizes[0] / 4;   // coords is [N,4]

    int n4 = (3*PLN + 64) / 4;
    zero_kernel<<<1024, 256>>>(n4);
    scatter_kernel<<<(n + 255) / 256, 256>>>(coords, voxels, n);
    weff_kernel<<<1, 256>>>(W1, W2, W3);

    // weights composed on device -> broadcast into constant bank (D2D, capturable)
    void* weff_dev = nullptr;
    cudaGetSymbolAddress(&weff_dev, g_weff);
    cudaMemcpyToSymbolAsync(c_w, weff_dev, sizeof(float)*6*6*9*8, 0,
                            cudaMemcpyDeviceToDevice);

    // y-blocks cover 8 outputs each: ceil(123/8) = 16
    conv_kernel<<<dim3(1, 16, OD * BB), 128>>>(b3, out);
}